// round 10
// baseline (speedup 1.0000x reference)
#include <cuda_runtime.h>
#include <math.h>

#define H 1024
#define V 50257
#define L 2
#define NGRP ((V + 7) / 8)     // 6283 row-groups of 8
#define GRID_GRU 352           // <= 444 (3 blocks/SM x 148 SMs) -> single wave
#define GRID_LOG 444           // <= 444 -> single wave

// Scratch (device globals; no allocation allowed; zero-initialized)
__device__ float g_x[H];            // GRU layer 0 output
__device__ float g_y[H];            // GRU layer 1 output (logits input)
__device__ float g_logits[V];
__device__ float g_sumexp;          // sum of exp(logit); reset in gru kernel
__device__ unsigned g_bar0, g_done0;  // gru kernel barrier
__device__ unsigned g_bar1, g_done1;  // logits kernel barrier

__device__ __forceinline__ float warp_sum(float s) {
    #pragma unroll
    for (int o = 16; o > 0; o >>= 1) s += __shfl_xor_sync(0xFFFFFFFF, s, o);
    return s;
}
__device__ __forceinline__ float sigmoidf_(float v) {
    return 1.0f / (1.0f + __expf(-v));
}

// Weight row via streaming global loads; vector via plain generic load
// (works for BOTH shared and global pointers — __ldg would trap on shared).
__device__ __forceinline__ float dot_row(const float4* __restrict__ wr,
                                         const float4* __restrict__ vv,
                                         int lane, bool do_relu) {
    float4 a[8], b[8];
    #pragma unroll
    for (int k = 0; k < 8; k++) a[k] = __ldcs(&wr[lane + 32 * k]);
    #pragma unroll
    for (int k = 0; k < 8; k++) b[k] = vv[lane + 32 * k];
    if (do_relu) {
        #pragma unroll
        for (int k = 0; k < 8; k++) {
            b[k].x = fmaxf(b[k].x, 0.0f); b[k].y = fmaxf(b[k].y, 0.0f);
            b[k].z = fmaxf(b[k].z, 0.0f); b[k].w = fmaxf(b[k].w, 0.0f);
        }
    }
    float s = 0.0f;
    #pragma unroll
    for (int k = 0; k < 8; k++)
        s += a[k].x * b[k].x + a[k].y * b[k].y + a[k].z * b[k].z + a[k].w * b[k].w;
    return warp_sum(s);
}

// Grid barrier for single-wave persistent kernels. All blocks resident by
// construction (grid <= min co-residency from __launch_bounds__).
__device__ __forceinline__ void grid_barrier(unsigned* bar, unsigned target) {
    __syncthreads();
    if (threadIdx.x == 0) {
        __threadfence();                    // publish this block's writes
        atomicAdd(bar, 1u);
        while (*(volatile unsigned*)bar < target) __nanosleep(64);
    }
    __syncthreads();
    __threadfence();                        // acquire others' writes
}

// Last block (by done-counter) resets the barrier pair for the next replay.
__device__ __forceinline__ void barrier_reset(unsigned* bar, unsigned* done,
                                              unsigned target) {
    __syncthreads();
    if (threadIdx.x == 0) {
        unsigned d = atomicAdd(done, 1u);
        if (d == target - 1) { *bar = 0u; *done = 0u; }
    }
}

// ---- Fused GRU: phase A = layer 0 (emb+relu fused), barrier, phase B = layer 1.
// grid = GRID_GRU blocks x 192 threads (6 warps), 3+ blocks/SM guaranteed.
__global__ __launch_bounds__(192, 3) void gru_fused_kernel(
    const long long* __restrict__ idx,
    const float* __restrict__ emb,
    const float* __restrict__ hidden,    // [L, H]
    const float* __restrict__ w_ih,      // [L, 3H, H]
    const float* __restrict__ w_hh,      // [L, 3H, H]
    const float* __restrict__ b_ih,      // [L, 3H]
    const float* __restrict__ b_hh,      // [L, 3H]
    float* __restrict__ out_hidden)      // [L, H] d_out slice
{
    int w = threadIdx.x >> 5;
    int lane = threadIdx.x & 31;
    __shared__ float sm[6];

    if (blockIdx.x == 0 && threadIdx.x == 33) g_sumexp = 0.0f;  // for logits kernel

    // ---- phase A: GRU layer 0 ----
    const float* x0 = emb + (size_t)idx[0] * H;   // relu applied in dot
    for (int j = blockIdx.x; j < H; j += GRID_GRU) {
        const float* vec = (w < 3) ? x0 : hidden;
        const float* W   = (w < 3) ? w_ih : w_hh;
        int row = (w % 3) * H + j;
        float s = dot_row(reinterpret_cast<const float4*>(W + (size_t)row * H),
                          reinterpret_cast<const float4*>(vec), lane, w < 3);
        __syncthreads();               // prior iteration's sm reads done
        if (lane == 0) sm[w] = s;
        __syncthreads();
        if (threadIdx.x == 0) {
            float i_r = sm[0] + b_ih[j];
            float i_z = sm[1] + b_ih[H + j];
            float i_n = sm[2] + b_ih[2 * H + j];
            float h_r = sm[3] + b_hh[j];
            float h_z = sm[4] + b_hh[H + j];
            float h_n = sm[5] + b_hh[2 * H + j];
            float r = sigmoidf_(i_r + h_r);
            float z = sigmoidf_(i_z + h_z);
            float n = tanhf(i_n + r * h_n);
            float hn = (1.0f - z) * n + z * hidden[j];
            g_x[j] = hn;
            out_hidden[j] = hn;
        }
    }

    grid_barrier(&g_bar0, GRID_GRU);

    // ---- phase B: GRU layer 1 (input = g_x) ----
    const float* w_ih1 = w_ih + 3 * H * H;
    const float* w_hh1 = w_hh + 3 * H * H;
    const float* b_ih1 = b_ih + 3 * H;
    const float* b_hh1 = b_hh + 3 * H;
    const float* h1 = hidden + H;
    for (int j = blockIdx.x; j < H; j += GRID_GRU) {
        const float* vec = (w < 3) ? g_x : h1;
        const float* W   = (w < 3) ? w_ih1 : w_hh1;
        int row = (w % 3) * H + j;
        float s = dot_row(reinterpret_cast<const float4*>(W + (size_t)row * H),
                          reinterpret_cast<const float4*>(vec), lane, false);
        __syncthreads();
        if (lane == 0) sm[w] = s;
        __syncthreads();
        if (threadIdx.x == 0) {
            float i_r = sm[0] + b_ih1[j];
            float i_z = sm[1] + b_ih1[H + j];
            float i_n = sm[2] + b_ih1[2 * H + j];
            float h_r = sm[3] + b_hh1[j];
            float h_z = sm[4] + b_hh1[H + j];
            float h_n = sm[5] + b_hh1[2 * H + j];
            float r = sigmoidf_(i_r + h_r);
            float z = sigmoidf_(i_z + h_z);
            float n = tanhf(i_n + r * h_n);
            float hn = (1.0f - z) * n + z * h1[j];
            g_y[j] = hn;
            out_hidden[H + j] = hn;
        }
    }

    barrier_reset(&g_bar0, &g_done0, GRID_GRU);
}

// ---- Fused logits + logsoftmax-write. grid = GRID_LOG x 256 threads.
// Phase A: grid-stride row-groups of 8, accumulate block-local sumexp,
// one atomicAdd per block. Barrier. Phase B: out = logit - log(sumexp). ----
__global__ __launch_bounds__(256, 3) void logits_fused_kernel(
    const float* __restrict__ w_out,
    const float* __restrict__ b_out,
    float* __restrict__ out)
{
    __shared__ float xs[H];
    __shared__ float rowv[8];
    for (int i = threadIdx.x; i < H; i += 256) xs[i] = g_y[i];
    __syncthreads();

    int wid = threadIdx.x >> 5;
    int lane = threadIdx.x & 31;
    const float4* vv = reinterpret_cast<const float4*>(xs);

    float acc = 0.0f;  // thread 0's block-local sumexp
    for (int grp = blockIdx.x; grp < NGRP; grp += GRID_LOG) {
        int row = grp * 8 + wid;
        bool valid = (row < V);
        float val = 0.0f;
        if (valid) {
            const float4* wr = reinterpret_cast<const float4*>(
                w_out + (size_t)row * H);
            float s = dot_row(wr, vv, lane, false);
            if (lane == 0) {
                val = s + b_out[row];
                g_logits[row] = val;
            }
        }
        __syncthreads();               // prior iteration's rowv reads done
        if (lane == 0) rowv[wid] = valid ? expf(val) : 0.0f;
        __syncthreads();
        if (threadIdx.x < 32) {
            float e = (lane < 8) ? rowv[lane] : 0.0f;
            float sum = warp_sum(e);
            if (lane == 0) acc += sum;
        }
    }
    if (threadIdx.x == 0) atomicAdd(&g_sumexp, acc);

    grid_barrier(&g_bar1, GRID_LOG);

    // ---- phase B: write logprobs ----
    float c = logf(*(volatile float*)&g_sumexp);
    const int V4 = V / 4;  // 12564
    for (int i = blockIdx.x * 256 + threadIdx.x; i < V4; i += GRID_LOG * 256) {
        float4 v = reinterpret_cast<const float4*>(g_logits)[i];
        v.x -= c; v.y -= c; v.z -= c; v.w -= c;
        reinterpret_cast<float4*>(out)[i] = v;
    }
    if (blockIdx.x == 0 && threadIdx.x == 0)
        out[V - 1] = g_logits[V - 1] - c;   // tail (V % 4 == 1)

    barrier_reset(&g_bar1, &g_done1, GRID_LOG);
}

extern "C" void kernel_launch(void* const* d_in, const int* in_sizes, int n_in,
                              void* d_out, int out_size) {
    const long long* idx  = (const long long*)d_in[0];
    const float* hidden   = (const float*)d_in[1];
    const float* emb      = (const float*)d_in[2];
    const float* w_ih     = (const float*)d_in[3];
    const float* w_hh     = (const float*)d_in[4];
    const float* b_ih     = (const float*)d_in[5];
    const float* b_hh     = (const float*)d_in[6];
    const float* w_out    = (const float*)d_in[7];
    const float* b_out    = (const float*)d_in[8];

    float* out = (float*)d_out;
    float* out_logprobs = out;       // [V]
    float* out_hidden   = out + V;   // [L, 1, H]

    gru_fused_kernel<<<GRID_GRU, 192>>>(idx, emb, hidden,
                                        w_ih, w_hh, b_ih, b_hh,
                                        out_hidden);

    logits_fused_kernel<<<GRID_LOG, 256>>>(w_out, b_out, out_logprobs);
}